// round 13
// baseline (speedup 1.0000x reference)
#include <cuda_runtime.h>
#include <cuda_fp16.h>
#include <cstdint>
#include <cmath>

#define PP 512
#define CC 65536
#define TILE_C 32
#define NTHREADS 256
// dynamic smem: xs 8192 u32 (32 KB) + A ring 8 warps * 4 stages * 2 KB (64 KB)
#define DSMEM_BYTES (32768 + 65536)

// A: softmaxed, fp16-rounded, packed in m16n8k16 A-fragment order:
//   g_A[(((mt*32 + k16)*32 + lane)*4 + regidx]  (uint32 = fp16x2)
__device__ uint32_t g_A[PP * PP / 2];

__device__ __forceinline__ uint32_t smem_u32(const void* p) {
    uint32_t a;
    asm("{ .reg .u64 t; cvta.to.shared.u64 t, %1; cvt.u32.u64 %0, t; }"
        : "=r"(a) : "l"(p));
    return a;
}

#define CP_ASYNC16(dst, src) \
    asm volatile("cp.async.ca.shared.global [%0], [%1], 16;" \
                 :: "r"(dst), "l"(src) : "memory")
#define CP_COMMIT() asm volatile("cp.async.commit_group;" ::: "memory")
#define CP_WAIT3()  asm volatile("cp.async.wait_group 3;"  ::: "memory")

// ---------------------------------------------------------------------------
// Kernel 1: softmax rows of rule_weights[r,0,:] -> g_A (fp16x2, frag-packed)
// ---------------------------------------------------------------------------
__global__ void ilp_softmax_kernel(const float* __restrict__ rw) {
    const int r = blockIdx.x;
    const int tid = threadIdx.x;
    const float* wrow = rw + r * PP;

    __shared__ float wbuf[8];
    __shared__ float s_mx, s_inv;

    float2 v = *(const float2*)&wrow[2 * tid];

    float m = fmaxf(v.x, v.y);
    #pragma unroll
    for (int o = 16; o; o >>= 1) m = fmaxf(m, __shfl_xor_sync(0xffffffffu, m, o));
    if ((tid & 31) == 0) wbuf[tid >> 5] = m;
    __syncthreads();
    if (tid == 0) {
        float mm = wbuf[0];
        #pragma unroll
        for (int w = 1; w < 8; ++w) mm = fmaxf(mm, wbuf[w]);
        s_mx = mm;
    }
    __syncthreads();

    float e0 = expf(v.x - s_mx);
    float e1 = expf(v.y - s_mx);
    float s = e0 + e1;
    #pragma unroll
    for (int o = 16; o; o >>= 1) s += __shfl_xor_sync(0xffffffffu, s, o);
    if ((tid & 31) == 0) wbuf[tid >> 5] = s;
    __syncthreads();
    if (tid == 0) {
        float ss = 0.f;
        #pragma unroll
        for (int w = 0; w < 8; ++w) ss += wbuf[w];
        s_inv = 1.0f / ss;
    }
    __syncthreads();

    const int mt     = r >> 4;
    const int row_in = r & 15;
    const int k16    = tid >> 3;
    const int lane   = ((row_in & 7) << 2) | (tid & 3);
    const int regidx = ((row_in >> 3) & 1) | (((tid >> 2) & 1) << 1);

    __half2 h2 = __floats2half2_rn(e0 * s_inv, e1 * s_inv);
    g_A[(((mt * 32 + k16) * 32 + lane) << 2) | regidx] = *(const uint32_t*)&h2;
}

// ---------------------------------------------------------------------------
// Kernel 2: fused forward chaining via mma.sync m16n8k16 f16 (fp32 accum).
//   CTA: 32 columns, 2 CTAs/SM. Warp w: rows [64w,64w+64):
//   4 m-tiles x 4 n-tiles -> 64 fp32 accumulators.
//   A staged through a WARP-PRIVATE 4-stage cp.async ring: each thread
//   cp.asyncs exactly the bytes it later LDSes itself -> per-thread
//   wait_group is the only synchronization (no barriers in the k-loop).
//   Running col-max M folded into B fragments at load (8 hmax2/step).
// ---------------------------------------------------------------------------

__device__ __forceinline__ uint32_t hmax2u(uint32_t a, uint32_t b) {
    __half2 r = __hmax2(*(__half2*)&a, *(__half2*)&b);
    return *(uint32_t*)&r;
}

__global__ void __launch_bounds__(NTHREADS, 2)
ilp_mma_kernel(const float* __restrict__ facts,
               const int* __restrict__ nit_ptr,
               float* __restrict__ out) {
    extern __shared__ uint32_t dsm[];
    uint32_t* xs  = dsm;                     // 8192 u32, B-frag packed fp16
    char*     Ast = (char*)(dsm + 8192);     // 8 warps x 4 stages x 2 KB
    __shared__ float s_M[TILE_C];
    __shared__ float s_red[8][TILE_C];

    const int tid  = threadIdx.x;
    const int wid  = tid >> 5;
    const int lane = tid & 31;
    const int cbase = blockIdx.x * TILE_C;

    if (tid < TILE_C) s_M[tid] = -INFINITY;

    // load f0 tile -> xs (fp16-round, B-frag pack); xs stays read-only after
    const int c4   = tid & 7;                // float4 col group (0..7)
    const int prow = tid >> 3;               // 0..31
    __half* xsh = (__half*)xs;
    for (int p = prow; p < PP; p += 32) {
        float4 v = *(const float4*)&facts[(size_t)p * CC + cbase + c4 * 4];
        const int k16 = p >> 4;
        const int bp  = (p >> 3) & 1;
        const int ln  = (p >> 1) & 3;
        const int hf  = p & 1;
        const float vv[4] = {v.x, v.y, v.z, v.w};
        #pragma unroll
        for (int j = 0; j < 4; ++j) {
            const int c = c4 * 4 + j;
            const int lane_d = ((c & 7) << 2) | ln;
            const int ntp = (c >> 4) & 1;
            const int q = (((c >> 3) & 1) << 1) | bp;
            xsh[((((k16 * 2 + ntp) * 32 + lane_d) << 2) | q) * 2 + hf] =
                __float2half_rn(vv[j]);
        }
    }
    __syncthreads();

    const int n_it = nit_ptr ? *nit_ptr : 3;
    const int crow = lane >> 2;              // column-in-group this thread uses

    // per-thread A source (uint4 granularity) and private ring addresses
    const uint4* Asrc = (const uint4*)g_A + (size_t)wid * 4096 + lane;
    const uint32_t ring0 = smem_u32(Ast) + wid * 8192 + lane * 16;
    const uint4* ringr = (const uint4*)(Ast + wid * 8192) + lane;
    const uint4* xs4 = (const uint4*)xs + lane;

    for (int it = 0; it < n_it; ++it) {
        // per-thread fp16x2-dup'd running max for its 4 column groups
        uint32_t Mh[4];
        #pragma unroll
        for (int j = 0; j < 4; ++j) {
            __half2 h = __float2half2_rn(s_M[crow + 8 * j]);
            Mh[j] = *(uint32_t*)&h;
        }

        float acc[4][4][4];
        #pragma unroll
        for (int mt = 0; mt < 4; ++mt)
            #pragma unroll
            for (int nt = 0; nt < 4; ++nt)
                #pragma unroll
                for (int q = 0; q < 4; ++q) acc[mt][nt][q] = 0.f;

        // prologue: issue stages 0..2 (one commit-group per stage)
        #pragma unroll
        for (int s = 0; s < 3; ++s) {
            #pragma unroll
            for (int mt = 0; mt < 4; ++mt)
                CP_ASYNC16(ring0 + (uint32_t)(s * 2048 + mt * 512),
                           Asrc + mt * 1024 + s * 32);
            CP_COMMIT();
        }

        #pragma unroll 4
        for (int k16 = 0; k16 < 32; ++k16) {
            // issue stage k16+3 into ring slot (k16+3)&3; always commit
            if (k16 + 3 < 32) {
                #pragma unroll
                for (int mt = 0; mt < 4; ++mt)
                    CP_ASYNC16(ring0 + (uint32_t)((((k16 + 3) & 3) * 2048) + mt * 512),
                               Asrc + mt * 1024 + (k16 + 3) * 32);
            }
            CP_COMMIT();

            // stage k16's group is complete when <=3 newer groups pend
            CP_WAIT3();

            // consume: A frags from private ring slot, B frags from xs
            const uint4* stg = ringr + (k16 & 3) * 128;   // 2048 B / 16
            uint4 ap[4];
            #pragma unroll
            for (int mt = 0; mt < 4; ++mt) ap[mt] = stg[mt * 32];

            uint4 bf[2];
            bf[0] = xs4[k16 * 64];
            bf[1] = xs4[k16 * 64 + 32];
            // fold running col-max once per loaded word (8 hmax2/step)
            bf[0].x = hmax2u(bf[0].x, Mh[0]);
            bf[0].y = hmax2u(bf[0].y, Mh[0]);
            bf[0].z = hmax2u(bf[0].z, Mh[1]);
            bf[0].w = hmax2u(bf[0].w, Mh[1]);
            bf[1].x = hmax2u(bf[1].x, Mh[2]);
            bf[1].y = hmax2u(bf[1].y, Mh[2]);
            bf[1].z = hmax2u(bf[1].z, Mh[3]);
            bf[1].w = hmax2u(bf[1].w, Mh[3]);

            #pragma unroll
            for (int mt = 0; mt < 4; ++mt) {
                const uint32_t a0 = ap[mt].x, a1 = ap[mt].y;
                const uint32_t a2 = ap[mt].z, a3 = ap[mt].w;
                #pragma unroll
                for (int nt = 0; nt < 4; ++nt) {
                    const uint32_t b0 = (nt & 1) ? ((nt >> 1) ? bf[1].z : bf[0].z)
                                                 : ((nt >> 1) ? bf[1].x : bf[0].x);
                    const uint32_t b1 = (nt & 1) ? ((nt >> 1) ? bf[1].w : bf[0].w)
                                                 : ((nt >> 1) ? bf[1].y : bf[0].y);
                    asm volatile(
                        "mma.sync.aligned.m16n8k16.row.col.f32.f16.f16.f32 "
                        "{%0,%1,%2,%3}, {%4,%5,%6,%7}, {%8,%9}, {%0,%1,%2,%3};"
                        : "+f"(acc[mt][nt][0]), "+f"(acc[mt][nt][1]),
                          "+f"(acc[mt][nt][2]), "+f"(acc[mt][nt][3])
                        : "r"(a0), "r"(a1), "r"(a2), "r"(a3),
                          "r"(b0), "r"(b1));
                }
            }
        }

        // epilogue: column max. d-frag: row=(lane>>2)(+8), col=(lane&3)*2(+1)
        #pragma unroll
        for (int nt = 0; nt < 4; ++nt) {
            float m0 = -INFINITY, m1 = -INFINITY;
            #pragma unroll
            for (int mt = 0; mt < 4; ++mt) {
                m0 = fmaxf(m0, fmaxf(acc[mt][nt][0], acc[mt][nt][2]));
                m1 = fmaxf(m1, fmaxf(acc[mt][nt][1], acc[mt][nt][3]));
            }
            #pragma unroll
            for (int o = 4; o <= 16; o <<= 1) {
                m0 = fmaxf(m0, __shfl_xor_sync(0xffffffffu, m0, o));
                m1 = fmaxf(m1, __shfl_xor_sync(0xffffffffu, m1, o));
            }
            if (lane < 4) {
                s_red[wid][nt * 8 + lane * 2 + 0] = m0;
                s_red[wid][nt * 8 + lane * 2 + 1] = m1;
            }
        }
        __syncthreads();
        if (tid < TILE_C) {
            float mm = s_M[tid];
            #pragma unroll
            for (int w = 0; w < 8; ++w) mm = fmaxf(mm, s_red[w][tid]);
            s_M[tid] = mm;
        }
        __syncthreads();
    }

    // output: max(exact f0, M_final), coalesced float4
    for (int p = prow; p < PP; p += 32) {
        float4 v = *(const float4*)&facts[(size_t)p * CC + cbase + c4 * 4];
        v.x = fmaxf(v.x, s_M[c4 * 4 + 0]);
        v.y = fmaxf(v.y, s_M[c4 * 4 + 1]);
        v.z = fmaxf(v.z, s_M[c4 * 4 + 2]);
        v.w = fmaxf(v.w, s_M[c4 * 4 + 3]);
        *(float4*)&out[(size_t)p * CC + cbase + c4 * 4] = v;
    }
}

// ---------------------------------------------------------------------------
extern "C" void kernel_launch(void* const* d_in, const int* in_sizes, int n_in,
                              void* d_out, int out_size) {
    (void)in_sizes; (void)out_size;
    const float* facts = (const float*)d_in[0];
    const float* rw    = (const float*)d_in[1];
    const int*   nit   = (n_in > 2) ? (const int*)d_in[2] : nullptr;
    float* out = (float*)d_out;

    cudaFuncSetAttribute(ilp_mma_kernel,
                         cudaFuncAttributeMaxDynamicSharedMemorySize, DSMEM_BYTES);

    ilp_softmax_kernel<<<PP, NTHREADS>>>(rw);
    ilp_mma_kernel<<<CC / TILE_C, NTHREADS, DSMEM_BYTES>>>(facts, nit, out);
}

// round 15
// speedup vs baseline: 1.4013x; 1.4013x over previous
#include <cuda_runtime.h>
#include <cuda_fp16.h>
#include <cstdint>
#include <cmath>

#define PP 512
#define CC 65536
#define TILE_C 32
#define NTHREADS 256

// A: softmaxed, fp16-rounded, packed in m16n8k16 A-fragment order:
//   g_A[(((mt*32 + k16)*32 + lane)*4 + regidx]  (uint32 = fp16x2)
__device__ uint32_t g_A[PP * PP / 2];

// ---------------------------------------------------------------------------
// Kernel 1: softmax rows of rule_weights[r,0,:] -> g_A (fp16x2, frag-packed)
// ---------------------------------------------------------------------------
__global__ void ilp_softmax_kernel(const float* __restrict__ rw) {
    const int r = blockIdx.x;
    const int tid = threadIdx.x;
    const float* wrow = rw + r * PP;

    __shared__ float wbuf[8];
    __shared__ float s_mx, s_inv;

    float2 v = *(const float2*)&wrow[2 * tid];

    float m = fmaxf(v.x, v.y);
    #pragma unroll
    for (int o = 16; o; o >>= 1) m = fmaxf(m, __shfl_xor_sync(0xffffffffu, m, o));
    if ((tid & 31) == 0) wbuf[tid >> 5] = m;
    __syncthreads();
    if (tid == 0) {
        float mm = wbuf[0];
        #pragma unroll
        for (int w = 1; w < 8; ++w) mm = fmaxf(mm, wbuf[w]);
        s_mx = mm;
    }
    __syncthreads();

    float e0 = expf(v.x - s_mx);
    float e1 = expf(v.y - s_mx);
    float s = e0 + e1;
    #pragma unroll
    for (int o = 16; o; o >>= 1) s += __shfl_xor_sync(0xffffffffu, s, o);
    if ((tid & 31) == 0) wbuf[tid >> 5] = s;
    __syncthreads();
    if (tid == 0) {
        float ss = 0.f;
        #pragma unroll
        for (int w = 0; w < 8; ++w) ss += wbuf[w];
        s_inv = 1.0f / ss;
    }
    __syncthreads();

    const int mt     = r >> 4;
    const int row_in = r & 15;
    const int k16    = tid >> 3;
    const int lane   = ((row_in & 7) << 2) | (tid & 3);
    const int regidx = ((row_in >> 3) & 1) | (((tid >> 2) & 1) << 1);

    __half2 h2 = __floats2half2_rn(e0 * s_inv, e1 * s_inv);
    g_A[(((mt * 32 + k16) * 32 + lane) << 2) | regidx] = *(const uint32_t*)&h2;
}

// ---------------------------------------------------------------------------
// Kernel 2: fused forward chaining via mma.sync m16n8k16 f16 (fp32 accum).
//   CTA: 32 columns, xs 32KB fp16 (READ-ONLY) -> 2 CTAs/SM.
//   Warp w: rows [64w,64w+64): 4 m-tiles x 4 n-tiles -> 64 fp32 accumulators.
//   Iteration 0 is PEELED with no M-fold (M=-INF is the identity there);
//   later iterations fold M into B fragments once at load (8 hmax2/step).
// ---------------------------------------------------------------------------

__device__ __forceinline__ uint32_t hmax2u(uint32_t a, uint32_t b) {
    __half2 r = __hmax2(*(__half2*)&a, *(__half2*)&b);
    return *(uint32_t*)&r;
}

// GEMM k-loop over 32 k16 steps; FOLD=1 applies hmax2(MHARR) to B fragments.
#define K_LOOP(FOLD, MHARR)                                                    \
    do {                                                                       \
        uint4 ap[2][4];                                                        \
        _Pragma("unroll")                                                      \
        for (int mt = 0; mt < 4; ++mt)                                         \
            ap[0][mt] = A4[(size_t)((wid * 4 + mt) * 32 + 0) * 32 + lane];     \
        _Pragma("unroll 2")                                                    \
        for (int k16 = 0; k16 < 32; ++k16) {                                   \
            const int cur = k16 & 1, nxt = cur ^ 1;                            \
            if (k16 + 1 < 32) {                                                \
                _Pragma("unroll")                                              \
                for (int mt = 0; mt < 4; ++mt)                                 \
                    ap[nxt][mt] =                                              \
                        A4[(size_t)((wid * 4 + mt) * 32 + (k16 + 1)) * 32 + lane]; \
            }                                                                  \
            uint4 bf[2];                                                       \
            _Pragma("unroll")                                                  \
            for (int ntp = 0; ntp < 2; ++ntp) {                                \
                bf[ntp] = xs4[(k16 * 2 + ntp) * 32 + lane];                    \
                if (FOLD) {                                                    \
                    bf[ntp].x = hmax2u(bf[ntp].x, (MHARR)[2 * ntp + 0]);       \
                    bf[ntp].y = hmax2u(bf[ntp].y, (MHARR)[2 * ntp + 0]);       \
                    bf[ntp].z = hmax2u(bf[ntp].z, (MHARR)[2 * ntp + 1]);       \
                    bf[ntp].w = hmax2u(bf[ntp].w, (MHARR)[2 * ntp + 1]);       \
                }                                                              \
            }                                                                  \
            _Pragma("unroll")                                                  \
            for (int mt = 0; mt < 4; ++mt) {                                   \
                const uint32_t a0 = ap[cur][mt].x, a1 = ap[cur][mt].y;         \
                const uint32_t a2 = ap[cur][mt].z, a3 = ap[cur][mt].w;         \
                _Pragma("unroll")                                              \
                for (int nt = 0; nt < 4; ++nt) {                               \
                    const uint32_t b0 = (nt & 1) ? ((nt >> 1) ? bf[1].z : bf[0].z) \
                                                 : ((nt >> 1) ? bf[1].x : bf[0].x); \
                    const uint32_t b1 = (nt & 1) ? ((nt >> 1) ? bf[1].w : bf[0].w) \
                                                 : ((nt >> 1) ? bf[1].y : bf[0].y); \
                    asm volatile(                                              \
                        "mma.sync.aligned.m16n8k16.row.col.f32.f16.f16.f32 "  \
                        "{%0,%1,%2,%3}, {%4,%5,%6,%7}, {%8,%9}, {%0,%1,%2,%3};" \
                        : "+f"(acc[mt][nt][0]), "+f"(acc[mt][nt][1]),          \
                          "+f"(acc[mt][nt][2]), "+f"(acc[mt][nt][3])           \
                        : "r"(a0), "r"(a1), "r"(a2), "r"(a3),                  \
                          "r"(b0), "r"(b1));                                   \
                }                                                              \
            }                                                                  \
        }                                                                      \
    } while (0)

// epilogue: per-warp column max -> s_red, then CTA reduce into s_M
#define EPILOGUE()                                                             \
    do {                                                                       \
        _Pragma("unroll")                                                      \
        for (int nt = 0; nt < 4; ++nt) {                                       \
            float m0 = -INFINITY, m1 = -INFINITY;                              \
            _Pragma("unroll")                                                  \
            for (int mt = 0; mt < 4; ++mt) {                                   \
                m0 = fmaxf(m0, fmaxf(acc[mt][nt][0], acc[mt][nt][2]));         \
                m1 = fmaxf(m1, fmaxf(acc[mt][nt][1], acc[mt][nt][3]));         \
            }                                                                  \
            _Pragma("unroll")                                                  \
            for (int o = 4; o <= 16; o <<= 1) {                                \
                m0 = fmaxf(m0, __shfl_xor_sync(0xffffffffu, m0, o));           \
                m1 = fmaxf(m1, __shfl_xor_sync(0xffffffffu, m1, o));           \
            }                                                                  \
            if (lane < 4) {                                                    \
                s_red[wid][nt * 8 + lane * 2 + 0] = m0;                        \
                s_red[wid][nt * 8 + lane * 2 + 1] = m1;                        \
            }                                                                  \
        }                                                                      \
        __syncthreads();                                                       \
        if (tid < TILE_C) {                                                    \
            float mm = s_M[tid];                                               \
            _Pragma("unroll")                                                  \
            for (int w = 0; w < 8; ++w) mm = fmaxf(mm, s_red[w][tid]);         \
            s_M[tid] = mm;                                                     \
        }                                                                      \
        __syncthreads();                                                       \
    } while (0)

__global__ void __launch_bounds__(NTHREADS, 2)
ilp_mma_kernel(const float* __restrict__ facts,
               const int* __restrict__ nit_ptr,
               float* __restrict__ out) {
    __shared__ __align__(16) uint32_t xs[PP * TILE_C / 2];  // 32 KB fp16
    __shared__ float s_M[TILE_C];
    __shared__ float s_red[8][TILE_C];

    const int tid  = threadIdx.x;
    const int wid  = tid >> 5;
    const int lane = tid & 31;
    const int cbase = blockIdx.x * TILE_C;

    if (tid < TILE_C) s_M[tid] = -INFINITY;

    // load f0 tile -> xs (fp16-round, B-frag pack); xs stays read-only after
    const int c4   = tid & 7;                        // float4 col group (0..7)
    const int prow = tid >> 3;                       // 0..31
    __half* xsh = (__half*)xs;
    for (int p = prow; p < PP; p += 32) {
        float4 v = *(const float4*)&facts[(size_t)p * CC + cbase + c4 * 4];
        const int k16 = p >> 4;
        const int bp  = (p >> 3) & 1;
        const int ln  = (p >> 1) & 3;
        const int hf  = p & 1;
        const float vv[4] = {v.x, v.y, v.z, v.w};
        #pragma unroll
        for (int j = 0; j < 4; ++j) {
            const int c = c4 * 4 + j;
            const int lane_d = ((c & 7) << 2) | ln;
            const int ntp = (c >> 4) & 1;
            const int q = (((c >> 3) & 1) << 1) | bp;
            xsh[((((k16 * 2 + ntp) * 32 + lane_d) << 2) | q) * 2 + hf] =
                __float2half_rn(vv[j]);
        }
    }
    __syncthreads();

    const int n_it = nit_ptr ? *nit_ptr : 3;
    const uint4* A4  = (const uint4*)g_A;
    const uint4* xs4 = (const uint4*)xs;
    const int crow = lane >> 2;   // column-in-group this thread consumes

    // ---- iteration 0 (peeled): M = -INF, no fold needed ----
    if (n_it > 0) {
        uint32_t MhDummy[4] = {0u, 0u, 0u, 0u};   // dead (FOLD=0), elided
        float acc[4][4][4];
        #pragma unroll
        for (int mt = 0; mt < 4; ++mt)
            #pragma unroll
            for (int nt = 0; nt < 4; ++nt)
                #pragma unroll
                for (int q = 0; q < 4; ++q) acc[mt][nt][q] = 0.f;

        K_LOOP(0, MhDummy);
        EPILOGUE();
    }

    // ---- iterations 1.. : fold running col-max into B at load ----
    for (int it = 1; it < n_it; ++it) {
        uint32_t Mh[4];
        #pragma unroll
        for (int j = 0; j < 4; ++j) {
            __half2 h = __float2half2_rn(s_M[crow + 8 * j]);
            Mh[j] = *(uint32_t*)&h;
        }

        float acc[4][4][4];
        #pragma unroll
        for (int mt = 0; mt < 4; ++mt)
            #pragma unroll
            for (int nt = 0; nt < 4; ++nt)
                #pragma unroll
                for (int q = 0; q < 4; ++q) acc[mt][nt][q] = 0.f;

        K_LOOP(1, Mh);
        EPILOGUE();
    }

    // output: max(exact f0, M_final), coalesced float4
    for (int p = prow; p < PP; p += 32) {
        float4 v = *(const float4*)&facts[(size_t)p * CC + cbase + c4 * 4];
        v.x = fmaxf(v.x, s_M[c4 * 4 + 0]);
        v.y = fmaxf(v.y, s_M[c4 * 4 + 1]);
        v.z = fmaxf(v.z, s_M[c4 * 4 + 2]);
        v.w = fmaxf(v.w, s_M[c4 * 4 + 3]);
        *(float4*)&out[(size_t)p * CC + cbase + c4 * 4] = v;
    }
}

// ---------------------------------------------------------------------------
extern "C" void kernel_launch(void* const* d_in, const int* in_sizes, int n_in,
                              void* d_out, int out_size) {
    (void)in_sizes; (void)out_size;
    const float* facts = (const float*)d_in[0];
    const float* rw    = (const float*)d_in[1];
    const int*   nit   = (n_in > 2) ? (const int*)d_in[2] : nullptr;
    float* out = (float*)d_out;

    ilp_softmax_kernel<<<PP, NTHREADS>>>(rw);
    ilp_mma_kernel<<<CC / TILE_C, NTHREADS>>>(facts, nit, out);
}

// round 16
// speedup vs baseline: 1.4364x; 1.0250x over previous
#include <cuda_runtime.h>
#include <cuda_fp16.h>
#include <cstdint>
#include <cmath>

#define PP 512
#define CC 65536
#define TILE_C 32
#define NTHREADS 256
// dynamic smem: xs 8192 u32 (32 KB, fp16 frag-packed) + xf32 16384 f32 (64 KB)
#define DSMEM_BYTES (32768 + 65536)

// A: softmaxed, fp16-rounded, packed in m16n8k16 A-fragment order:
//   g_A[(((mt*32 + k16)*32 + lane)*4 + regidx]  (uint32 = fp16x2)
__device__ uint32_t g_A[PP * PP / 2];

// ---------------------------------------------------------------------------
// Kernel 1: softmax rows of rule_weights[r,0,:] -> g_A (fp16x2, frag-packed)
// ---------------------------------------------------------------------------
__global__ void ilp_softmax_kernel(const float* __restrict__ rw) {
    const int r = blockIdx.x;
    const int tid = threadIdx.x;
    const float* wrow = rw + r * PP;

    __shared__ float wbuf[8];
    __shared__ float s_mx, s_inv;

    float2 v = *(const float2*)&wrow[2 * tid];

    float m = fmaxf(v.x, v.y);
    #pragma unroll
    for (int o = 16; o; o >>= 1) m = fmaxf(m, __shfl_xor_sync(0xffffffffu, m, o));
    if ((tid & 31) == 0) wbuf[tid >> 5] = m;
    __syncthreads();
    if (tid == 0) {
        float mm = wbuf[0];
        #pragma unroll
        for (int w = 1; w < 8; ++w) mm = fmaxf(mm, wbuf[w]);
        s_mx = mm;
    }
    __syncthreads();

    float e0 = expf(v.x - s_mx);
    float e1 = expf(v.y - s_mx);
    float s = e0 + e1;
    #pragma unroll
    for (int o = 16; o; o >>= 1) s += __shfl_xor_sync(0xffffffffu, s, o);
    if ((tid & 31) == 0) wbuf[tid >> 5] = s;
    __syncthreads();
    if (tid == 0) {
        float ss = 0.f;
        #pragma unroll
        for (int w = 0; w < 8; ++w) ss += wbuf[w];
        s_inv = 1.0f / ss;
    }
    __syncthreads();

    const int mt     = r >> 4;
    const int row_in = r & 15;
    const int k16    = tid >> 3;
    const int lane   = ((row_in & 7) << 2) | (tid & 3);
    const int regidx = ((row_in >> 3) & 1) | (((tid >> 2) & 1) << 1);

    __half2 h2 = __floats2half2_rn(e0 * s_inv, e1 * s_inv);
    g_A[(((mt * 32 + k16) * 32 + lane) << 2) | regidx] = *(const uint32_t*)&h2;
}

// ---------------------------------------------------------------------------
// Kernel 2: fused forward chaining via mma.sync m16n8k16 f16 (fp32 accum).
//   CTA: 32 columns, 2 CTAs/SM. Warp w: rows [64w,64w+64):
//   4 m-tiles x 4 n-tiles -> 64 fp32 accumulators.
//   Exact fp32 f0 tile kept in SMEM (xf32) so the output phase never touches
//   DRAM for reads. M folded into B fragments once at load (8 hmax2/step).
// ---------------------------------------------------------------------------

__device__ __forceinline__ uint32_t hmax2u(uint32_t a, uint32_t b) {
    __half2 r = __hmax2(*(__half2*)&a, *(__half2*)&b);
    return *(uint32_t*)&r;
}

__global__ void __launch_bounds__(NTHREADS, 2)
ilp_mma_kernel(const float* __restrict__ facts,
               const int* __restrict__ nit_ptr,
               float* __restrict__ out) {
    extern __shared__ uint32_t dsm[];
    uint32_t* xs   = dsm;                      // 8192 u32, B-frag packed fp16
    float*    xf32 = (float*)(dsm + 8192);     // 16384 f32, linear [p][c]
    __shared__ float s_M[TILE_C];
    __shared__ float s_red[8][TILE_C];

    const int tid  = threadIdx.x;
    const int wid  = tid >> 5;
    const int lane = tid & 31;
    const int cbase = blockIdx.x * TILE_C;

    if (tid < TILE_C) s_M[tid] = -INFINITY;

    // load f0 tile once: exact fp32 copy -> xf32; fp16 B-frag pack -> xs
    const int c4   = tid & 7;                  // float4 col group (0..7)
    const int prow = tid >> 3;                 // 0..31
    __half* xsh = (__half*)xs;
    for (int p = prow; p < PP; p += 32) {
        float4 v = *(const float4*)&facts[(size_t)p * CC + cbase + c4 * 4];
        *(float4*)&xf32[p * TILE_C + c4 * 4] = v;
        const int k16 = p >> 4;
        const int bp  = (p >> 3) & 1;
        const int ln  = (p >> 1) & 3;
        const int hf  = p & 1;
        const float vv[4] = {v.x, v.y, v.z, v.w};
        #pragma unroll
        for (int j = 0; j < 4; ++j) {
            const int c = c4 * 4 + j;
            const int lane_d = ((c & 7) << 2) | ln;
            const int ntp = (c >> 4) & 1;
            const int q = (((c >> 3) & 1) << 1) | bp;
            xsh[((((k16 * 2 + ntp) * 32 + lane_d) << 2) | q) * 2 + hf] =
                __float2half_rn(vv[j]);
        }
    }
    __syncthreads();

    const int n_it = nit_ptr ? *nit_ptr : 3;
    const uint4* A4  = (const uint4*)g_A;
    const uint4* xs4 = (const uint4*)xs;
    const int crow = lane >> 2;   // column-in-group this thread consumes

    for (int it = 0; it < n_it; ++it) {
        // per-thread fp16x2-dup'd running max for its 4 column groups
        uint32_t Mh[4];
        #pragma unroll
        for (int j = 0; j < 4; ++j) {
            __half2 h = __float2half2_rn(s_M[crow + 8 * j]);
            Mh[j] = *(uint32_t*)&h;
        }

        float acc[4][4][4];
        #pragma unroll
        for (int mt = 0; mt < 4; ++mt)
            #pragma unroll
            for (int nt = 0; nt < 4; ++nt)
                #pragma unroll
                for (int q = 0; q < 4; ++q) acc[mt][nt][q] = 0.f;

        uint4 ap[2][4];
        #pragma unroll
        for (int mt = 0; mt < 4; ++mt)
            ap[0][mt] = A4[(size_t)((wid * 4 + mt) * 32 + 0) * 32 + lane];

        #pragma unroll 2
        for (int k16 = 0; k16 < 32; ++k16) {
            const int cur = k16 & 1, nxt = cur ^ 1;
            if (k16 + 1 < 32) {
                #pragma unroll
                for (int mt = 0; mt < 4; ++mt)
                    ap[nxt][mt] =
                        A4[(size_t)((wid * 4 + mt) * 32 + (k16 + 1)) * 32 + lane];
            }
            uint4 bf[2];
            #pragma unroll
            for (int ntp = 0; ntp < 2; ++ntp) {
                bf[ntp] = xs4[(k16 * 2 + ntp) * 32 + lane];
                // fold running col-max once per loaded word (8 hmax2/step)
                bf[ntp].x = hmax2u(bf[ntp].x, Mh[2 * ntp + 0]);
                bf[ntp].y = hmax2u(bf[ntp].y, Mh[2 * ntp + 0]);
                bf[ntp].z = hmax2u(bf[ntp].z, Mh[2 * ntp + 1]);
                bf[ntp].w = hmax2u(bf[ntp].w, Mh[2 * ntp + 1]);
            }

            #pragma unroll
            for (int mt = 0; mt < 4; ++mt) {
                const uint32_t a0 = ap[cur][mt].x, a1 = ap[cur][mt].y;
                const uint32_t a2 = ap[cur][mt].z, a3 = ap[cur][mt].w;
                #pragma unroll
                for (int nt = 0; nt < 4; ++nt) {
                    const uint32_t b0 = (nt & 1) ? ((nt >> 1) ? bf[1].z : bf[0].z)
                                                 : ((nt >> 1) ? bf[1].x : bf[0].x);
                    const uint32_t b1 = (nt & 1) ? ((nt >> 1) ? bf[1].w : bf[0].w)
                                                 : ((nt >> 1) ? bf[1].y : bf[0].y);
                    asm volatile(
                        "mma.sync.aligned.m16n8k16.row.col.f32.f16.f16.f32 "
                        "{%0,%1,%2,%3}, {%4,%5,%6,%7}, {%8,%9}, {%0,%1,%2,%3};"
                        : "+f"(acc[mt][nt][0]), "+f"(acc[mt][nt][1]),
                          "+f"(acc[mt][nt][2]), "+f"(acc[mt][nt][3])
                        : "r"(a0), "r"(a1), "r"(a2), "r"(a3),
                          "r"(b0), "r"(b1));
                }
            }
        }

        // epilogue: column max. d-frag: row=(lane>>2)(+8), col=(lane&3)*2(+1)
        #pragma unroll
        for (int nt = 0; nt < 4; ++nt) {
            float m0 = -INFINITY, m1 = -INFINITY;
            #pragma unroll
            for (int mt = 0; mt < 4; ++mt) {
                m0 = fmaxf(m0, fmaxf(acc[mt][nt][0], acc[mt][nt][2]));
                m1 = fmaxf(m1, fmaxf(acc[mt][nt][1], acc[mt][nt][3]));
            }
            #pragma unroll
            for (int o = 4; o <= 16; o <<= 1) {
                m0 = fmaxf(m0, __shfl_xor_sync(0xffffffffu, m0, o));
                m1 = fmaxf(m1, __shfl_xor_sync(0xffffffffu, m1, o));
            }
            if (lane < 4) {
                s_red[wid][nt * 8 + lane * 2 + 0] = m0;
                s_red[wid][nt * 8 + lane * 2 + 1] = m1;
            }
        }
        __syncthreads();
        if (tid < TILE_C) {
            float mm = s_M[tid];
            #pragma unroll
            for (int w = 0; w < 8; ++w) mm = fmaxf(mm, s_red[w][tid]);
            s_M[tid] = mm;
        }
        __syncthreads();
    }

    // output: max(exact f0 from SMEM, M_final) -> coalesced float4 stores.
    // No DRAM reads in this phase.
    const float M0 = s_M[c4 * 4 + 0];
    const float M1 = s_M[c4 * 4 + 1];
    const float M2 = s_M[c4 * 4 + 2];
    const float M3 = s_M[c4 * 4 + 3];
    for (int p = prow; p < PP; p += 32) {
        float4 v = *(const float4*)&xf32[p * TILE_C + c4 * 4];
        v.x = fmaxf(v.x, M0);
        v.y = fmaxf(v.y, M1);
        v.z = fmaxf(v.z, M2);
        v.w = fmaxf(v.w, M3);
        *(float4*)&out[(size_t)p * CC + cbase + c4 * 4] = v;
    }
}

// ---------------------------------------------------------------------------
extern "C" void kernel_launch(void* const* d_in, const int* in_sizes, int n_in,
                              void* d_out, int out_size) {
    (void)in_sizes; (void)out_size;
    const float* facts = (const float*)d_in[0];
    const float* rw    = (const float*)d_in[1];
    const int*   nit   = (n_in > 2) ? (const int*)d_in[2] : nullptr;
    float* out = (float*)d_out;

    cudaFuncSetAttribute(ilp_mma_kernel,
                         cudaFuncAttributeMaxDynamicSharedMemorySize, DSMEM_BYTES);

    ilp_softmax_kernel<<<PP, NTHREADS>>>(rw);
    ilp_mma_kernel<<<CC / TILE_C, NTHREADS, DSMEM_BYTES>>>(facts, nit, out);
}